// round 2
// baseline (speedup 1.0000x reference)
#include <cuda_runtime.h>
#include <cuda_bf16.h>
#include <cstdint>

// ---------------------------------------------------------------------------
// FMoE top-1 dispatch + grouped SGEMM
//   out[t, :] = weight[gate[t]] @ inp[t, :]
// inp   : [N_TOK, IN_FEAT]  f32
// gate  : [N_TOK]           i32
// weight: [N_EXP, OUT_FEAT, IN_FEAT] f32
// out   : [N_TOK, OUT_FEAT] f32
// ---------------------------------------------------------------------------

#define N_TOK_MAX 8192
#define N_EXP     8
#define IN_FEAT   1024
#define OUT_FEAT  1024

#define BM 128
#define BN 128
#define BK 8
#define TM 8
#define TN 8

// Scratch (allocation-free: __device__ globals)
__device__ int g_cnt[N_EXP];
__device__ int g_off[N_EXP];
__device__ int g_cur[N_EXP];
__device__ int g_idx[N_TOK_MAX];

__global__ void k_zero() {
    int t = threadIdx.x;
    if (t < N_EXP) { g_cnt[t] = 0; g_cur[t] = 0; }
}

__global__ void k_count(const int* __restrict__ gate, int n) {
    int i = blockIdx.x * blockDim.x + threadIdx.x;
    if (i < n) atomicAdd(&g_cnt[gate[i]], 1);
}

__global__ void k_scan() {
    if (threadIdx.x == 0) {
        int s = 0;
        for (int e = 0; e < N_EXP; e++) { g_off[e] = s; s += g_cnt[e]; }
    }
}

__global__ void k_scatter(const int* __restrict__ gate, int n) {
    int i = blockIdx.x * blockDim.x + threadIdx.x;
    if (i < n) {
        int e = gate[i];
        int p = atomicAdd(&g_cur[e], 1);
        g_idx[g_off[e] + p] = i;
    }
}

// Grouped SGEMM: gridDim = (OUT_FEAT/BN, maxTilesM, N_EXP)
// Each block: BM gathered tokens x BN output features, K = IN_FEAT.
__global__ __launch_bounds__(256, 2)
void k_gemm(const float* __restrict__ inp,
            const float* __restrict__ weight,
            float* __restrict__ out)
{
    const int e    = blockIdx.z;
    const int cnt  = g_cnt[e];
    const int m0   = blockIdx.y * BM;
    if (m0 >= cnt) return;               // ragged over-provisioned tiles exit
    const int n0   = blockIdx.x * BN;
    const int base = g_off[e];

    const float* We = weight + (size_t)e * OUT_FEAT * IN_FEAT;

    __shared__ float As[BK][BM];
    __shared__ float Bs[BK][BN];

    const int tid = threadIdx.x;

    // ---- global-load assignments ----
    // A: 128 rows x 8 k-cols. 2 threads per row, each loads one float4.
    const int arow  = tid >> 1;          // 0..127
    const int acol4 = (tid & 1) * 4;     // 0 or 4
    const int gm    = m0 + arow;
    const bool avalid = (gm < cnt);
    const int atok  = avalid ? g_idx[base + gm] : 0;   // safe dummy row
    const float* Arow = inp + (size_t)atok * IN_FEAT;

    // B: 128 n-rows x 8 k-cols, same scheme. out = inp @ W^T so
    // Bs[k][n] = We[(n0+n)*IN_FEAT + k0 + k]
    const int brow  = tid >> 1;
    const int bcol4 = (tid & 1) * 4;
    const float* Brow = We + (size_t)(n0 + brow) * IN_FEAT;

    // ---- compute assignment: 16x16 thread grid, 8x8 micro-tile ----
    const int trow = tid >> 4;           // 0..15
    const int tcol = tid & 15;           // 0..15

    float acc[TM][TN];
    #pragma unroll
    for (int i = 0; i < TM; i++)
        #pragma unroll
        for (int j = 0; j < TN; j++)
            acc[i][j] = 0.0f;

    for (int k0 = 0; k0 < IN_FEAT; k0 += BK) {
        const float4 a = *reinterpret_cast<const float4*>(Arow + k0 + acol4);
        const float4 b = *reinterpret_cast<const float4*>(Brow + k0 + bcol4);
        __syncthreads();
        As[acol4 + 0][arow] = a.x;
        As[acol4 + 1][arow] = a.y;
        As[acol4 + 2][arow] = a.z;
        As[acol4 + 3][arow] = a.w;
        Bs[bcol4 + 0][brow] = b.x;
        Bs[bcol4 + 1][brow] = b.y;
        Bs[bcol4 + 2][brow] = b.z;
        Bs[bcol4 + 3][brow] = b.w;
        __syncthreads();

        #pragma unroll
        for (int k = 0; k < BK; k++) {
            float ar[TM], br[TN];
            #pragma unroll
            for (int i = 0; i < TM; i++) ar[i] = As[k][trow * TM + i];
            #pragma unroll
            for (int j = 0; j < TN; j++) br[j] = Bs[k][tcol * TN + j];
            #pragma unroll
            for (int i = 0; i < TM; i++)
                #pragma unroll
                for (int j = 0; j < TN; j++)
                    acc[i][j] = fmaf(ar[i], br[j], acc[i][j]);
        }
    }

    // ---- scatter C rows back to token order ----
    #pragma unroll
    for (int i = 0; i < TM; i++) {
        const int gmi = m0 + trow * TM + i;
        if (gmi < cnt) {
            const int tok = g_idx[base + gmi];
            float* orow = out + (size_t)tok * OUT_FEAT + n0 + tcol * TN;
            float4 v0 = make_float4(acc[i][0], acc[i][1], acc[i][2], acc[i][3]);
            float4 v1 = make_float4(acc[i][4], acc[i][5], acc[i][6], acc[i][7]);
            *reinterpret_cast<float4*>(orow + 0) = v0;
            *reinterpret_cast<float4*>(orow + 4) = v1;
        }
    }
}

extern "C" void kernel_launch(void* const* d_in, const int* in_sizes, int n_in,
                              void* d_out, int out_size)
{
    const float* inp  = (const float*)d_in[0];
    const int*   gate = (const int*)d_in[1];
    const float* w    = (const float*)d_in[2];
    float*       out  = (float*)d_out;

    const int n = in_sizes[1];           // number of tokens

    k_zero<<<1, 32>>>();
    k_count<<<(n + 255) / 256, 256>>>(gate, n);
    k_scan<<<1, 1>>>();
    k_scatter<<<(n + 255) / 256, 256>>>(gate, n);

    dim3 grid(OUT_FEAT / BN, (n + BM - 1) / BM, N_EXP);
    k_gemm<<<grid, 256>>>(inp, w, out);
}

// round 8
// speedup vs baseline: 2.5791x; 2.5791x over previous
#include <cuda_runtime.h>
#include <cuda_bf16.h>
#include <cstdint>

// ---------------------------------------------------------------------------
// FMoE top-1 dispatch + grouped GEMM via mma.sync (bf16 split-precision).
//   out[t, :] = weight[gate[t]] @ inp[t, :]
// fp32 x -> hi=bf16(x), lo=bf16(x-hi);  acc += Ahi*Bhi + Ahi*Blo + Alo*Bhi
// NOTE: harness compiles PTX at compute_103 (base family) -> tcgen05 is
// unavailable; mma.sync/ldmatrix/cp.async are the legal tensor path.
// R8 fixes vs R7: (1) B ldmatrix must be NON-trans (SMEM B is [n][k], k
// contiguous, exactly the row.col B fragment); (2) cp.async tail must
// wait_group 0 on the final chunk (its own load is the newest group).
// ---------------------------------------------------------------------------

#define N_TOK_MAX 8192
#define N_EXP     8
#define IN_FEAT   1024
#define OUT_FEAT  1024

#define BM 128
#define BN 128
#define K_BLK 64                        // bf16 elems per k-chunk
#define NCHUNK (IN_FEAT / K_BLK)        // 16
#define ROW_U4 (IN_FEAT * 2 / 16)       // 128 uint4 per bf16 row

// ---------------- scratch (__device__ globals; allocation-free) ------------
__device__ uint4 g_inp_hi[(size_t)N_TOK_MAX * ROW_U4];
__device__ uint4 g_inp_lo[(size_t)N_TOK_MAX * ROW_U4];
__device__ uint4 g_w_hi[(size_t)N_EXP * OUT_FEAT * ROW_U4];
__device__ uint4 g_w_lo[(size_t)N_EXP * OUT_FEAT * ROW_U4];

__device__ int g_cnt[N_EXP];
__device__ int g_off[N_EXP];
__device__ int g_cur[N_EXP];
__device__ int g_idx[N_TOK_MAX];

// ---------------- PTX helpers ----------------------------------------------
__device__ __forceinline__ uint32_t smem_u32(const void* p) {
    uint32_t a;
    asm("{ .reg .u64 t; cvta.to.shared.u64 t, %1; cvt.u32.u64 %0, t; }"
        : "=r"(a) : "l"(p));
    return a;
}

__device__ __forceinline__ void cp16(uint32_t dst, const void* src) {
    asm volatile("cp.async.cg.shared.global [%0], [%1], 16;"
                 :: "r"(dst), "l"(src) : "memory");
}
#define CP_COMMIT() asm volatile("cp.async.commit_group;" ::: "memory")
#define CP_WAIT1()  asm volatile("cp.async.wait_group 1;" ::: "memory")
#define CP_WAIT0()  asm volatile("cp.async.wait_group 0;" ::: "memory")

#define LDSM_X4(r, a)                                                         \
    asm volatile("ldmatrix.sync.aligned.m8n8.x4.shared.b16 {%0,%1,%2,%3}, [%4];" \
                 : "=r"((r)[0]), "=r"((r)[1]), "=r"((r)[2]), "=r"((r)[3])     \
                 : "r"(a))

#define MMA_BF16(c, a, b0, b1)                                                \
    asm volatile("mma.sync.aligned.m16n8k16.row.col.f32.bf16.bf16.f32 "       \
                 "{%0,%1,%2,%3}, {%4,%5,%6,%7}, {%8,%9}, {%0,%1,%2,%3};"      \
                 : "+f"((c)[0]), "+f"((c)[1]), "+f"((c)[2]), "+f"((c)[3])     \
                 : "r"((a)[0]), "r"((a)[1]), "r"((a)[2]), "r"((a)[3]),        \
                   "r"(b0), "r"(b1))

// ---------------- dispatch kernels -----------------------------------------
__global__ void k_zero() {
    int t = threadIdx.x;
    if (t < N_EXP) { g_cnt[t] = 0; g_cur[t] = 0; }
}
__global__ void k_count(const int* __restrict__ gate, int n) {
    int i = blockIdx.x * blockDim.x + threadIdx.x;
    if (i < n) atomicAdd(&g_cnt[gate[i]], 1);
}
__global__ void k_scan() {
    if (threadIdx.x == 0) {
        int s = 0;
        for (int e = 0; e < N_EXP; e++) { g_off[e] = s; s += g_cnt[e]; }
    }
}
__global__ void k_scatter(const int* __restrict__ gate, int n) {
    int i = blockIdx.x * blockDim.x + threadIdx.x;
    if (i < n) {
        int e = gate[i];
        int p = atomicAdd(&g_cur[e], 1);
        g_idx[g_off[e] + p] = i;
    }
}

// ---------------- split fp32 -> (bf16 hi, bf16 lo), both tensors ------------
__global__ void k_split(const float* __restrict__ inp, const float* __restrict__ w,
                        int n8_inp, int n8_w) {
    int i = blockIdx.x * blockDim.x + threadIdx.x;
    const float* src;
    uint4 *hi, *lo;
    int j;
    if (i < n8_inp) { src = inp; hi = g_inp_hi; lo = g_inp_lo; j = i; }
    else if (i < n8_inp + n8_w) { src = w; hi = g_w_hi; lo = g_w_lo; j = i - n8_inp; }
    else return;

    const float4* s = reinterpret_cast<const float4*>(src) + (size_t)j * 2;
    float4 a = s[0], b = s[1];
    float f[8] = {a.x, a.y, a.z, a.w, b.x, b.y, b.z, b.w};
    uint32_t hb[8], lb[8];
#pragma unroll
    for (int k = 0; k < 8; k++) {
        __nv_bfloat16 h = __float2bfloat16(f[k]);
        float r = f[k] - __bfloat162float(h);
        __nv_bfloat16 l = __float2bfloat16(r);
        hb[k] = (uint32_t)__bfloat16_as_ushort(h);
        lb[k] = (uint32_t)__bfloat16_as_ushort(l);
    }
    uint4 H, L;
    H.x = hb[0] | (hb[1] << 16); H.y = hb[2] | (hb[3] << 16);
    H.z = hb[4] | (hb[5] << 16); H.w = hb[6] | (hb[7] << 16);
    L.x = lb[0] | (lb[1] << 16); L.y = lb[2] | (lb[3] << 16);
    L.z = lb[4] | (lb[5] << 16); L.w = lb[6] | (lb[7] << 16);
    hi[j] = H; lo[j] = L;
}

// ---------------- mma.sync grouped GEMM -------------------------------------
// SMEM: 3 stages x 64KB; each stage: A_hi/A_lo/B_hi/B_lo, 128 rows x 128B,
// chunk-XOR swizzle (c ^= row&7) for conflict-free ldmatrix.
#define STAGES      3
#define STAGE_BYTES 65536
#define OFF_AHI     0
#define OFF_ALO     16384
#define OFF_BHI     32768
#define OFF_BLO     49152
#define SMEM_TOTAL  (1024 + STAGES * STAGE_BYTES)

__global__ __launch_bounds__(256, 1)
void k_gemm_mma(float* __restrict__ out)
{
    const int e   = blockIdx.z;
    const int cnt = g_cnt[e];
    const int m0  = blockIdx.y * BM;
    if (m0 >= cnt) return;
    const int n0   = blockIdx.x * BN;
    const int base = g_off[e];

    extern __shared__ char smem[];
    const uint32_t sbase = smem_u32(smem);
    const uint32_t tb0   = (sbase + 1023u) & ~1023u;   // aligned tile region

    const int tid    = threadIdx.x;
    const int lane   = tid & 31;
    const int wid    = tid >> 5;
    const int warp_m = wid & 3;        // 4 warps over M (32 rows each)
    const int warp_n = wid >> 2;       // 2 warps over N (64 cols each)

    // ---- cp.async loader assignment: row = tid>>1, 4 x 16B chunks ---------
    const int row = tid >> 1;
    const int ub  = (tid & 1) * 4;
    const int gm  = m0 + row;
    const int atok = (gm < cnt) ? g_idx[base + gm] : g_idx[base];

    const uint4* pAh = g_inp_hi + (size_t)atok * ROW_U4 + ub;
    const uint4* pAl = g_inp_lo + (size_t)atok * ROW_U4 + ub;
    const uint4* pBh = g_w_hi + ((size_t)e * OUT_FEAT + (n0 + row)) * ROW_U4 + ub;
    const uint4* pBl = g_w_lo + ((size_t)e * OUT_FEAT + (n0 + row)) * ROW_U4 + ub;

    uint32_t dsw[4];
#pragma unroll
    for (int u = 0; u < 4; u++)
        dsw[u] = row * 128 + (((ub + u) ^ (row & 7)) << 4);

    // ---- ldmatrix lane addressing (all NON-trans) --------------------------
    // A frag m16n8k16: a_i from 8x8 tiles (m0..m3) = (rows0-7,k0-7),
    // (rows8-15,k0-7), (rows0-7,k8-15), (rows8-15,k8-15).
    const int a_r  = warp_m * 32 + (lane & 15);
    const int a_cb = lane >> 4;
    // B frag: SMEM holds [n][k] (k contiguous) == row.col B operand layout.
    // tiles: (n0-7,k0-7), (n0-7,k8-15), (n8-15,k0-7), (n8-15,k8-15)
    const int b_r  = warp_n * 64 + (lane & 7) + ((lane >> 4) << 3);
    const int b_cb = (lane >> 3) & 1;

    float acc[2][8][4];
#pragma unroll
    for (int mf = 0; mf < 2; mf++)
#pragma unroll
        for (int nf = 0; nf < 8; nf++)
#pragma unroll
            for (int q = 0; q < 4; q++) acc[mf][nf][q] = 0.0f;

    // ---- pipeline ----------------------------------------------------------
#define LOAD_STAGE(kb, st) do {                                               \
        const uint32_t tbs = tb0 + (st) * STAGE_BYTES;                        \
        const int kof = (kb) * 8;                                             \
        _Pragma("unroll")                                                     \
        for (int u = 0; u < 4; u++) {                                         \
            cp16(tbs + OFF_AHI + dsw[u], pAh + kof + u);                      \
            cp16(tbs + OFF_ALO + dsw[u], pAl + kof + u);                      \
            cp16(tbs + OFF_BHI + dsw[u], pBh + kof + u);                      \
            cp16(tbs + OFF_BLO + dsw[u], pBl + kof + u);                      \
        }                                                                     \
        CP_COMMIT();                                                          \
    } while (0)

    LOAD_STAGE(0, 0);
    LOAD_STAGE(1, 1);

    for (int kb = 0; kb < NCHUNK; kb++) {
        const int st = kb % STAGES;
        if (kb == NCHUNK - 1) CP_WAIT0(); else CP_WAIT1();
        __syncthreads();
        const uint32_t tbs = tb0 + st * STAGE_BYTES;

#pragma unroll
        for (int ks = 0; ks < 4; ks++) {
            uint32_t ahi[2][4], alo[2][4];
#pragma unroll
            for (int mf = 0; mf < 2; mf++) {
                const int r = a_r + mf * 16;
                const int c = ks * 2 + a_cb;
                const uint32_t off = r * 128 + ((c ^ (r & 7)) << 4);
                LDSM_X4(ahi[mf], tbs + OFF_AHI + off);
                LDSM_X4(alo[mf], tbs + OFF_ALO + off);
            }
            uint32_t bhi[4][4], blo[4][4];
#pragma unroll
            for (int g4 = 0; g4 < 4; g4++) {
                const int r = b_r + g4 * 16;
                const int c = ks * 2 + b_cb;
                const uint32_t off = r * 128 + ((c ^ (r & 7)) << 4);
                LDSM_X4(bhi[g4], tbs + OFF_BHI + off);
                LDSM_X4(blo[g4], tbs + OFF_BLO + off);
            }
#pragma unroll
            for (int mf = 0; mf < 2; mf++)
#pragma unroll
                for (int nf = 0; nf < 8; nf++) {
                    const int g4 = nf >> 1, pp = (nf & 1) * 2;
                    MMA_BF16(acc[mf][nf], ahi[mf], bhi[g4][pp], bhi[g4][pp + 1]);
                    MMA_BF16(acc[mf][nf], ahi[mf], blo[g4][pp], blo[g4][pp + 1]);
                    MMA_BF16(acc[mf][nf], alo[mf], bhi[g4][pp], bhi[g4][pp + 1]);
                }
        }

        if (kb + 2 < NCHUNK) LOAD_STAGE(kb + 2, (kb + 2) % STAGES);
    }

    // ---- epilogue: scatter C rows back to token order ----------------------
    const int g = lane >> 2;
    const int t = lane & 3;
#pragma unroll
    for (int mf = 0; mf < 2; mf++) {
#pragma unroll
        for (int hh = 0; hh < 2; hh++) {
            const int m = m0 + warp_m * 32 + mf * 16 + g + hh * 8;
            if (m < cnt) {
                const int tok = g_idx[base + m];
                float* orow = out + (size_t)tok * OUT_FEAT + n0 + warp_n * 64 + t * 2;
#pragma unroll
                for (int nf = 0; nf < 8; nf++) {
                    float2 v = make_float2(acc[mf][nf][hh * 2],
                                           acc[mf][nf][hh * 2 + 1]);
                    *reinterpret_cast<float2*>(orow + nf * 8) = v;
                }
            }
        }
    }
}

// ---------------- launch -----------------------------------------------------
extern "C" void kernel_launch(void* const* d_in, const int* in_sizes, int n_in,
                              void* d_out, int out_size)
{
    const float* inp  = (const float*)d_in[0];
    const int*   gate = (const int*)d_in[1];
    const float* w    = (const float*)d_in[2];
    float*       out  = (float*)d_out;

    const int n = in_sizes[1];                       // token count

    cudaFuncSetAttribute(k_gemm_mma,
                         cudaFuncAttributeMaxDynamicSharedMemorySize, SMEM_TOTAL);

    k_zero<<<1, 32>>>();
    k_count<<<(n + 255) / 256, 256>>>(gate, n);
    k_scan<<<1, 1>>>();
    k_scatter<<<(n + 255) / 256, 256>>>(gate, n);

    const int n8_inp = n * IN_FEAT / 8;
    const int n8_w   = N_EXP * OUT_FEAT * IN_FEAT / 8;
    const int n8     = n8_inp + n8_w;
    k_split<<<(n8 + 255) / 256, 256>>>(inp, w, n8_inp, n8_w);

    dim3 grid(OUT_FEAT / BN, (n + BM - 1) / BM, N_EXP);
    k_gemm_mma<<<grid, 256, SMEM_TOTAL>>>(out);
}

// round 9
// speedup vs baseline: 3.3620x; 1.3035x over previous
#include <cuda_runtime.h>
#include <cuda_fp16.h>
#include <cstdint>

// ---------------------------------------------------------------------------
// FMoE top-1 dispatch + grouped GEMM via mma.sync, fp16 split-precision 2-MMA:
//   out[t, :] = weight[gate[t]] @ inp[t, :]
// fp32 x -> hi=fp16(x), lo=fp16(x-hi);  acc += Ahi*Bhi + Ahi*Blo  (fp32 accum)
// Dropped Alo*Bhi term costs ~1.5e-4 rel err (fp16 has 11 mantissa bits),
// well under the 1e-3 threshold, and cuts MMAs by 1/3 vs 3-term bf16.
// Dispatch: fixed per-expert slabs (8192) -> no count/scan; scatter fused
// into the split kernel. 3 launches total.
// ---------------------------------------------------------------------------

#define N_TOK_MAX 8192
#define N_EXP     8
#define IN_FEAT   1024
#define OUT_FEAT  1024

#define BM 128
#define BN 128
#define K_BLK 64                        // fp16 elems per k-chunk
#define NCHUNK (IN_FEAT / K_BLK)        // 16
#define ROW_U4 (IN_FEAT * 2 / 16)       // 128 uint4 per fp16 row

// ---------------- scratch (__device__ globals; allocation-free) ------------
__device__ uint4 g_inp_h[(size_t)N_TOK_MAX * ROW_U4];
__device__ uint4 g_w_h[(size_t)N_EXP * OUT_FEAT * ROW_U4];
__device__ uint4 g_w_l[(size_t)N_EXP * OUT_FEAT * ROW_U4];

__device__ int g_cnt[N_EXP];
__device__ int g_idx[N_EXP * N_TOK_MAX];   // fixed slab per expert

// ---------------- PTX helpers ----------------------------------------------
__device__ __forceinline__ uint32_t smem_u32(const void* p) {
    uint32_t a;
    asm("{ .reg .u64 t; cvta.to.shared.u64 t, %1; cvt.u32.u64 %0, t; }"
        : "=r"(a) : "l"(p));
    return a;
}

__device__ __forceinline__ void cp16(uint32_t dst, const void* src) {
    asm volatile("cp.async.cg.shared.global [%0], [%1], 16;"
                 :: "r"(dst), "l"(src) : "memory");
}
#define CP_COMMIT() asm volatile("cp.async.commit_group;" ::: "memory")
#define CP_WAIT(n)  asm volatile("cp.async.wait_group %0;" :: "n"(n) : "memory")

#define LDSM_X4(r, a)                                                         \
    asm volatile("ldmatrix.sync.aligned.m8n8.x4.shared.b16 {%0,%1,%2,%3}, [%4];" \
                 : "=r"((r)[0]), "=r"((r)[1]), "=r"((r)[2]), "=r"((r)[3])     \
                 : "r"(a))

#define MMA_F16(c, a, b0, b1)                                                 \
    asm volatile("mma.sync.aligned.m16n8k16.row.col.f32.f16.f16.f32 "         \
                 "{%0,%1,%2,%3}, {%4,%5,%6,%7}, {%8,%9}, {%0,%1,%2,%3};"      \
                 : "+f"((c)[0]), "+f"((c)[1]), "+f"((c)[2]), "+f"((c)[3])     \
                 : "r"((a)[0]), "r"((a)[1]), "r"((a)[2]), "r"((a)[3]),        \
                   "r"(b0), "r"(b1))

// ---------------- kernel 1: zero counters ----------------------------------
__global__ void k_zero() {
    int t = threadIdx.x;
    if (t < N_EXP) g_cnt[t] = 0;
}

// ---------------- kernel 2: scatter + fp16 hi/lo split ----------------------
// Thread ranges: [0,n) scatter; [n, n+n8i) inp split (hi only);
// [n+n8i, n+n8i+n8w) weight split (hi+lo).
__global__ void k_prep(const float* __restrict__ inp,
                       const float* __restrict__ w,
                       const int* __restrict__ gate,
                       int n, int n8i, int n8w)
{
    int i = blockIdx.x * blockDim.x + threadIdx.x;

    if (i < n) {                                   // token -> expert slab
        int e = gate[i];
        int p = atomicAdd(&g_cnt[e], 1);
        g_idx[e * N_TOK_MAX + p] = i;
        return;
    }
    int j = i - n;
    if (j < n8i) {                                 // inp: hi only
        const float4* s = reinterpret_cast<const float4*>(inp) + (size_t)j * 2;
        float4 a = s[0], b = s[1];
        float f[8] = {a.x, a.y, a.z, a.w, b.x, b.y, b.z, b.w};
        uint32_t hb[8];
#pragma unroll
        for (int k = 0; k < 8; k++)
            hb[k] = (uint32_t)__half_as_ushort(__float2half_rn(f[k]));
        uint4 H;
        H.x = hb[0] | (hb[1] << 16); H.y = hb[2] | (hb[3] << 16);
        H.z = hb[4] | (hb[5] << 16); H.w = hb[6] | (hb[7] << 16);
        g_inp_h[j] = H;
        return;
    }
    j -= n8i;
    if (j < n8w) {                                 // weight: hi + lo
        const float4* s = reinterpret_cast<const float4*>(w) + (size_t)j * 2;
        float4 a = s[0], b = s[1];
        float f[8] = {a.x, a.y, a.z, a.w, b.x, b.y, b.z, b.w};
        uint32_t hb[8], lb[8];
#pragma unroll
        for (int k = 0; k < 8; k++) {
            __half h = __float2half_rn(f[k]);
            __half l = __float2half_rn(f[k] - __half2float(h));
            hb[k] = (uint32_t)__half_as_ushort(h);
            lb[k] = (uint32_t)__half_as_ushort(l);
        }
        uint4 H, L;
        H.x = hb[0] | (hb[1] << 16); H.y = hb[2] | (hb[3] << 16);
        H.z = hb[4] | (hb[5] << 16); H.w = hb[6] | (hb[7] << 16);
        L.x = lb[0] | (lb[1] << 16); L.y = lb[2] | (lb[3] << 16);
        L.z = lb[4] | (lb[5] << 16); L.w = lb[6] | (lb[7] << 16);
        g_w_h[j] = H; g_w_l[j] = L;
    }
}

// ---------------- kernel 3: mma.sync grouped GEMM ---------------------------
// SMEM: 4 stages x 48KB; each stage: A_hi / B_hi / B_lo, 128 rows x 128B,
// chunk-XOR swizzle (c ^= row&7) for conflict-free ldmatrix.
#define STAGES      4
#define STAGE_BYTES 49152
#define OFF_AHI     0
#define OFF_BHI     16384
#define OFF_BLO     32768
#define SMEM_TOTAL  (1024 + STAGES * STAGE_BYTES)

__global__ __launch_bounds__(256, 1)
void k_gemm_mma(float* __restrict__ out)
{
    const int e   = blockIdx.z;
    const int cnt = g_cnt[e];
    const int m0  = blockIdx.y * BM;
    if (m0 >= cnt) return;
    const int n0   = blockIdx.x * BN;
    const int base = e * N_TOK_MAX;

    extern __shared__ char smem[];
    const uint32_t sbase = smem_u32(smem);
    const uint32_t tb0   = (sbase + 1023u) & ~1023u;

    const int tid    = threadIdx.x;
    const int lane   = tid & 31;
    const int wid    = tid >> 5;
    const int warp_m = wid & 3;        // 4 warps over M (32 rows each)
    const int warp_n = wid >> 2;       // 2 warps over N (64 cols each)

    // ---- cp.async loader: row = tid>>1, 4 x 16B units per row half ---------
    const int row = tid >> 1;
    const int ub  = (tid & 1) * 4;
    const int gm  = m0 + row;
    const int atok = (gm < cnt) ? g_idx[base + gm] : g_idx[base];

    const uint4* pAh = g_inp_h + (size_t)atok * ROW_U4 + ub;
    const uint4* pBh = g_w_h + ((size_t)e * OUT_FEAT + (n0 + row)) * ROW_U4 + ub;
    const uint4* pBl = g_w_l + ((size_t)e * OUT_FEAT + (n0 + row)) * ROW_U4 + ub;

    uint32_t dsw[4];
#pragma unroll
    for (int u = 0; u < 4; u++)
        dsw[u] = row * 128 + (((ub + u) ^ (row & 7)) << 4);

    // ---- ldmatrix lane addressing (non-trans) ------------------------------
    const int a_r  = warp_m * 32 + (lane & 15);
    const int a_cb = lane >> 4;
    const int b_r  = warp_n * 64 + (lane & 7) + ((lane >> 4) << 3);
    const int b_cb = (lane >> 3) & 1;

    float acc[2][8][4];
#pragma unroll
    for (int mf = 0; mf < 2; mf++)
#pragma unroll
        for (int nf = 0; nf < 8; nf++)
#pragma unroll
            for (int q = 0; q < 4; q++) acc[mf][nf][q] = 0.0f;

#define LOAD_STAGE(kb, st) do {                                               \
        const uint32_t tbs = tb0 + (st) * STAGE_BYTES;                        \
        const int kof = (kb) * 8;                                             \
        _Pragma("unroll")                                                     \
        for (int u = 0; u < 4; u++) {                                         \
            cp16(tbs + OFF_AHI + dsw[u], pAh + kof + u);                      \
            cp16(tbs + OFF_BHI + dsw[u], pBh + kof + u);                      \
            cp16(tbs + OFF_BLO + dsw[u], pBl + kof + u);                      \
        }                                                                     \
        CP_COMMIT();                                                          \
    } while (0)

    LOAD_STAGE(0, 0);
    LOAD_STAGE(1, 1);
    LOAD_STAGE(2, 2);

    for (int kb = 0; kb < NCHUNK; kb++) {
        const int st = kb & 3;
        // commits issued after stage kb's: min(3, NCHUNK-1-kb)
        if (kb < NCHUNK - 2)      CP_WAIT(2);
        else if (kb == NCHUNK - 2) CP_WAIT(1);
        else                       CP_WAIT(0);
        __syncthreads();
        const uint32_t tbs = tb0 + st * STAGE_BYTES;

#pragma unroll
        for (int ks = 0; ks < 4; ks++) {
            uint32_t ahi[2][4];
#pragma unroll
            for (int mf = 0; mf < 2; mf++) {
                const int r = a_r + mf * 16;
                const int c = ks * 2 + a_cb;
                const uint32_t off = r * 128 + ((c ^ (r & 7)) << 4);
                LDSM_X4(ahi[mf], tbs + OFF_AHI + off);
            }
            uint32_t bhi[4][4], blo[4][4];
#pragma unroll
            for (int g4 = 0; g4 < 4; g4++) {
                const int r = b_r + g4 * 16;
                const int c = ks * 2 + b_cb;
                const uint32_t off = r * 128 + ((c ^ (r & 7)) << 4);
                LDSM_X4(bhi[g4], tbs + OFF_BHI + off);
                LDSM_X4(blo[g4], tbs + OFF_BLO + off);
            }
#pragma unroll
            for (int mf = 0; mf < 2; mf++)
#pragma unroll
                for (int nf = 0; nf < 8; nf++) {
                    const int g4 = nf >> 1, pp = (nf & 1) * 2;
                    MMA_F16(acc[mf][nf], ahi[mf], bhi[g4][pp], bhi[g4][pp + 1]);
                    MMA_F16(acc[mf][nf], ahi[mf], blo[g4][pp], blo[g4][pp + 1]);
                }
        }

        if (kb + 3 < NCHUNK) LOAD_STAGE(kb + 3, (kb + 3) & 3);
    }

    // ---- epilogue: scatter C rows back to token order ----------------------
    const int g = lane >> 2;
    const int t = lane & 3;
#pragma unroll
    for (int mf = 0; mf < 2; mf++) {
#pragma unroll
        for (int hh = 0; hh < 2; hh++) {
            const int m = m0 + warp_m * 32 + mf * 16 + g + hh * 8;
            if (m < cnt) {
                const int tok = g_idx[base + m];
                float* orow = out + (size_t)tok * OUT_FEAT + n0 + warp_n * 64 + t * 2;
#pragma unroll
                for (int nf = 0; nf < 8; nf++) {
                    float2 v = make_float2(acc[mf][nf][hh * 2],
                                           acc[mf][nf][hh * 2 + 1]);
                    *reinterpret_cast<float2*>(orow + nf * 8) = v;
                }
            }
        }
    }
}

// ---------------- launch -----------------------------------------------------
extern "C" void kernel_launch(void* const* d_in, const int* in_sizes, int n_in,
                              void* d_out, int out_size)
{
    const float* inp  = (const float*)d_in[0];
    const int*   gate = (const int*)d_in[1];
    const float* w    = (const float*)d_in[2];
    float*       out  = (float*)d_out;

    const int n = in_sizes[1];                       // token count

    cudaFuncSetAttribute(k_gemm_mma,
                         cudaFuncAttributeMaxDynamicSharedMemorySize, SMEM_TOTAL);

    const int n8i = n * IN_FEAT / 8;
    const int n8w = N_EXP * OUT_FEAT * IN_FEAT / 8;
    const int total = n + n8i + n8w;

    k_zero<<<1, 32>>>();
    k_prep<<<(total + 255) / 256, 256>>>(inp, w, gate, n, n8i, n8w);

    dim3 grid(OUT_FEAT / BN, N_TOK_MAX / BM, N_EXP);
    k_gemm_mma<<<grid, 256, SMEM_TOTAL>>>(out);
}

// round 13
// speedup vs baseline: 5.1313x; 1.5263x over previous
#include <cuda_runtime.h>
#include <cuda_fp16.h>
#include <cstdint>

// ---------------------------------------------------------------------------
// FMoE top-1 dispatch + grouped GEMM via mma.sync, pure fp16 (fp32 accum):
//   out[t, :] = weight[gate[t]] @ inp[t, :]
// R12 = R10/R11 resubmitted (third attempt): both prior attempts died at the
// broker with no harness output. This kernel is a strict simplification of
// the PASSING R9 kernel (same instruction set, less SMEM, fewer globals,
// identical pipeline schedule), so a kernel-induced container kill has no
// mechanism; treating as infra outage. If this fails too, next round runs
// the bit-exact R9 kernel as the definitive infra-vs-kernel experiment.
// Error model (validated R9): pure fp16 -> ~2.9e-4 rel err, 3.4x under 1e-3.
// Dispatch: fixed per-expert slabs (8192) -> no count/scan; scatter fused
// into the prep kernel. 3 launches total.
// ---------------------------------------------------------------------------

#define N_TOK_MAX 8192
#define N_EXP     8
#define IN_FEAT   1024
#define OUT_FEAT  1024

#define BM 128
#define BN 128
#define K_BLK 64                        // fp16 elems per k-chunk
#define NCHUNK (IN_FEAT / K_BLK)        // 16
#define ROW_U4 (IN_FEAT * 2 / 16)       // 128 uint4 per fp16 row

// ---------------- scratch (__device__ globals; allocation-free) ------------
__device__ uint4 g_inp_h[(size_t)N_TOK_MAX * ROW_U4];
__device__ uint4 g_w_h[(size_t)N_EXP * OUT_FEAT * ROW_U4];

__device__ int g_cnt[N_EXP];
__device__ int g_idx[N_EXP * N_TOK_MAX];   // fixed slab per expert

// ---------------- PTX helpers ----------------------------------------------
__device__ __forceinline__ uint32_t smem_u32(const void* p) {
    uint32_t a;
    asm("{ .reg .u64 t; cvta.to.shared.u64 t, %1; cvt.u32.u64 %0, t; }"
        : "=r"(a) : "l"(p));
    return a;
}

__device__ __forceinline__ void cp16(uint32_t dst, const void* src) {
    asm volatile("cp.async.cg.shared.global [%0], [%1], 16;"
                 :: "r"(dst), "l"(src) : "memory");
}
#define CP_COMMIT() asm volatile("cp.async.commit_group;" ::: "memory")
#define CP_WAIT(n)  asm volatile("cp.async.wait_group %0;" :: "n"(n) : "memory")

#define LDSM_X4(r, a)                                                         \
    asm volatile("ldmatrix.sync.aligned.m8n8.x4.shared.b16 {%0,%1,%2,%3}, [%4];" \
                 : "=r"((r)[0]), "=r"((r)[1]), "=r"((r)[2]), "=r"((r)[3])     \
                 : "r"(a))

#define MMA_F16(c, a, b0, b1)                                                 \
    asm volatile("mma.sync.aligned.m16n8k16.row.col.f32.f16.f16.f32 "         \
                 "{%0,%1,%2,%3}, {%4,%5,%6,%7}, {%8,%9}, {%0,%1,%2,%3};"      \
                 : "+f"((c)[0]), "+f"((c)[1]), "+f"((c)[2]), "+f"((c)[3])     \
                 : "r"((a)[0]), "r"((a)[1]), "r"((a)[2]), "r"((a)[3]),        \
                   "r"(b0), "r"(b1))

// ---------------- kernel 1: zero counters ----------------------------------
__global__ void k_zero() {
    int t = threadIdx.x;
    if (t < N_EXP) g_cnt[t] = 0;
}

// ---------------- kernel 2: scatter + fp16 convert --------------------------
// Thread ranges: [0,n) scatter; [n, n+n8i) inp convert; then weight convert.
__global__ void k_prep(const float* __restrict__ inp,
                       const float* __restrict__ w,
                       const int* __restrict__ gate,
                       int n, int n8i, int n8w)
{
    int i = blockIdx.x * blockDim.x + threadIdx.x;

    if (i < n) {                                   // token -> expert slab
        int e = gate[i];
        int p = atomicAdd(&g_cnt[e], 1);
        g_idx[e * N_TOK_MAX + p] = i;
        return;
    }
    int j = i - n;
    const float* src;
    uint4* dst;
    if (j < n8i) { src = inp; dst = g_inp_h; }
    else {
        j -= n8i;
        if (j >= n8w) return;
        src = w; dst = g_w_h;
    }
    const float4* s = reinterpret_cast<const float4*>(src) + (size_t)j * 2;
    float4 a = s[0], b = s[1];
    float f[8] = {a.x, a.y, a.z, a.w, b.x, b.y, b.z, b.w};
    uint32_t hb[8];
#pragma unroll
    for (int k = 0; k < 8; k++)
        hb[k] = (uint32_t)__half_as_ushort(__float2half_rn(f[k]));
    uint4 H;
    H.x = hb[0] | (hb[1] << 16); H.y = hb[2] | (hb[3] << 16);
    H.z = hb[4] | (hb[5] << 16); H.w = hb[6] | (hb[7] << 16);
    dst[j] = H;
}

// ---------------- kernel 3: mma.sync grouped GEMM ---------------------------
// SMEM: 4 stages x 32KB; each stage: A / B tiles, 128 rows x 128B,
// chunk-XOR swizzle (c ^= row&7) for conflict-free ldmatrix.
#define STAGES      4
#define STAGE_BYTES 32768
#define OFF_A       0
#define OFF_B       16384
#define SMEM_TOTAL  (1024 + STAGES * STAGE_BYTES)

__global__ __launch_bounds__(256, 1)
void k_gemm_mma(float* __restrict__ out)
{
    const int e   = blockIdx.z;
    const int cnt = g_cnt[e];
    const int m0  = blockIdx.y * BM;
    if (m0 >= cnt) return;
    const int n0   = blockIdx.x * BN;
    const int base = e * N_TOK_MAX;

    extern __shared__ char smem[];
    const uint32_t sbase = smem_u32(smem);
    const uint32_t tb0   = (sbase + 1023u) & ~1023u;

    const int tid    = threadIdx.x;
    const int lane   = tid & 31;
    const int wid    = tid >> 5;
    const int warp_m = wid & 3;        // 4 warps over M (32 rows each)
    const int warp_n = wid >> 2;       // 2 warps over N (64 cols each)

    // ---- cp.async loader: row = tid>>1, 4 x 16B units per row half ---------
    const int row = tid >> 1;
    const int ub  = (tid & 1) * 4;
    const int gm  = m0 + row;
    const int atok = (gm < cnt) ? g_idx[base + gm] : g_idx[base];

    const uint4* pA = g_inp_h + (size_t)atok * ROW_U4 + ub;
    const uint4* pB = g_w_h + ((size_t)e * OUT_FEAT + (n0 + row)) * ROW_U4 + ub;

    uint32_t dsw[4];
#pragma unroll
    for (int u = 0; u < 4; u++)
        dsw[u] = row * 128 + (((ub + u) ^ (row & 7)) << 4);

    // ---- ldmatrix lane addressing (non-trans) ------------------------------
    const int a_r  = warp_m * 32 + (lane & 15);
    const int a_cb = lane >> 4;
    const int b_r  = warp_n * 64 + (lane & 7) + ((lane >> 4) << 3);
    const int b_cb = (lane >> 3) & 1;

    float acc[2][8][4];
#pragma unroll
    for (int mf = 0; mf < 2; mf++)
#pragma unroll
        for (int nf = 0; nf < 8; nf++)
#pragma unroll
            for (int q = 0; q < 4; q++) acc[mf][nf][q] = 0.0f;

#define LOAD_STAGE(kb, st) do {                                               \
        const uint32_t tbs = tb0 + (st) * STAGE_BYTES;                        \
        const int kof = (kb) * 8;                                             \
        _Pragma("unroll")                                                     \
        for (int u = 0; u < 4; u++) {                                         \
            cp16(tbs + OFF_A + dsw[u], pA + kof + u);                         \
            cp16(tbs + OFF_B + dsw[u], pB + kof + u);                         \
        }                                                                     \
        CP_COMMIT();                                                          \
    } while (0)

    LOAD_STAGE(0, 0);
    LOAD_STAGE(1, 1);
    LOAD_STAGE(2, 2);

    for (int kb = 0; kb < NCHUNK; kb++) {
        const int st = kb & 3;
        if (kb < NCHUNK - 2)       CP_WAIT(2);
        else if (kb == NCHUNK - 2) CP_WAIT(1);
        else                       CP_WAIT(0);
        __syncthreads();
        const uint32_t tbs = tb0 + st * STAGE_BYTES;

#pragma unroll
        for (int ks = 0; ks < 4; ks++) {
            uint32_t af[2][4];
#pragma unroll
            for (int mf = 0; mf < 2; mf++) {
                const int r = a_r + mf * 16;
                const int c = ks * 2 + a_cb;
                const uint32_t off = r * 128 + ((c ^ (r & 7)) << 4);
                LDSM_X4(af[mf], tbs + OFF_A + off);
            }
            uint32_t bf[4][4];
#pragma unroll
            for (int g4 = 0; g4 < 4; g4++) {
                const int r = b_r + g4 * 16;
                const int c = ks * 2 + b_cb;
                const uint32_t off = r * 128 + ((c ^ (r & 7)) << 4);
                LDSM_X4(bf[g4], tbs + OFF_B + off);
            }
#pragma unroll
            for (int mf = 0; mf < 2; mf++)
#pragma unroll
                for (int nf = 0; nf < 8; nf++) {
                    const int g4 = nf >> 1, pp = (nf & 1) * 2;
                    MMA_F16(acc[mf][nf], af[mf], bf[g4][pp], bf[g4][pp + 1]);
                }
        }

        if (kb + 3 < NCHUNK) LOAD_STAGE(kb + 3, (kb + 3) & 3);
    }

    // ---- epilogue: scatter C rows back to token order ----------------------
    const int g = lane >> 2;
    const int t = lane & 3;
#pragma unroll
    for (int mf = 0; mf < 2; mf++) {
#pragma unroll
        for (int hh = 0; hh < 2; hh++) {
            const int m = m0 + warp_m * 32 + mf * 16 + g + hh * 8;
            if (m < cnt) {
                const int tok = g_idx[base + m];
                float* orow = out + (size_t)tok * OUT_FEAT + n0 + warp_n * 64 + t * 2;
#pragma unroll
                for (int nf = 0; nf < 8; nf++) {
                    float2 v = make_float2(acc[mf][nf][hh * 2],
                                           acc[mf][nf][hh * 2 + 1]);
                    *reinterpret_cast<float2*>(orow + nf * 8) = v;
                }
            }
        }
    }
}

// ---------------- launch -----------------------------------------------------
extern "C" void kernel_launch(void* const* d_in, const int* in_sizes, int n_in,
                              void* d_out, int out_size)
{
    const float* inp  = (const float*)d_in[0];
    const int*   gate = (const int*)d_in[1];
    const float* w    = (const float*)d_in[2];
    float*       out  = (float*)d_out;

    const int n = in_sizes[1];                       // token count

    cudaFuncSetAttribute(k_gemm_mma,
                         cudaFuncAttributeMaxDynamicSharedMemorySize, SMEM_TOTAL);

    const int n8i = n * IN_FEAT / 8;
    const int n8w = N_EXP * OUT_FEAT * IN_FEAT / 8;
    const int total = n + n8i + n8w;

    k_zero<<<1, 32>>>();
    k_prep<<<(total + 255) / 256, 256>>>(inp, w, gate, n, n8i, n8w);

    dim3 grid(OUT_FEAT / BN, N_TOK_MAX / BM, N_EXP);
    k_gemm_mma<<<grid, 256, SMEM_TOTAL>>>(out);
}

// round 17
// speedup vs baseline: 5.7643x; 1.1234x over previous
#include <cuda_runtime.h>
#include <cuda_fp16.h>
#include <cstdint>

// ---------------------------------------------------------------------------
// FMoE top-1 dispatch + grouped GEMM via mma.sync, pure fp16 (fp32 accum):
//   out[t, :] = weight[gate[t]] @ inp[t, :]
// R17 vs R14: fixes the 3-stage ring bug that caused NaN. Invariant: chunk
// kb lives in stage kb%STAGES; the prefetch at iteration kb targets
// (kb+2)%STAGES (the stage consumed at kb-1, already past this iteration's
// barrier). R14 wrongly reused the just-consumed stage (kb%3) as the target,
// so chunk 2 was never where the consumer looked. Extra mid-loop barrier
// removed (not needed with the correct target).
// Retained from R14: memset node for counters, occupancy 2 (3x32KB stages,
// __launch_bounds__(256,2)).
// ---------------------------------------------------------------------------

#define N_TOK_MAX 8192
#define N_EXP     8
#define IN_FEAT   1024
#define OUT_FEAT  1024

#define BM 128
#define BN 128
#define K_BLK 64                        // fp16 elems per k-chunk
#define NCHUNK (IN_FEAT / K_BLK)        // 16
#define ROW_U4 (IN_FEAT * 2 / 16)       // 128 uint4 per fp16 row

// ---------------- scratch (__device__ globals; allocation-free) ------------
__device__ uint4 g_inp_h[(size_t)N_TOK_MAX * ROW_U4];
__device__ uint4 g_w_h[(size_t)N_EXP * OUT_FEAT * ROW_U4];

__device__ int g_cnt[N_EXP];
__device__ int g_idx[N_EXP * N_TOK_MAX];   // fixed slab per expert

// ---------------- PTX helpers ----------------------------------------------
__device__ __forceinline__ uint32_t smem_u32(const void* p) {
    uint32_t a;
    asm("{ .reg .u64 t; cvta.to.shared.u64 t, %1; cvt.u32.u64 %0, t; }"
        : "=r"(a) : "l"(p));
    return a;
}

__device__ __forceinline__ void cp16(uint32_t dst, const void* src) {
    asm volatile("cp.async.cg.shared.global [%0], [%1], 16;"
                 :: "r"(dst), "l"(src) : "memory");
}
#define CP_COMMIT() asm volatile("cp.async.commit_group;" ::: "memory")
#define CP_WAIT(n)  asm volatile("cp.async.wait_group %0;" :: "n"(n) : "memory")

#define LDSM_X4(r, a)                                                         \
    asm volatile("ldmatrix.sync.aligned.m8n8.x4.shared.b16 {%0,%1,%2,%3}, [%4];" \
                 : "=r"((r)[0]), "=r"((r)[1]), "=r"((r)[2]), "=r"((r)[3])     \
                 : "r"(a))

#define MMA_F16(c, a, b0, b1)                                                 \
    asm volatile("mma.sync.aligned.m16n8k16.row.col.f32.f16.f16.f32 "         \
                 "{%0,%1,%2,%3}, {%4,%5,%6,%7}, {%8,%9}, {%0,%1,%2,%3};"      \
                 : "+f"((c)[0]), "+f"((c)[1]), "+f"((c)[2]), "+f"((c)[3])     \
                 : "r"((a)[0]), "r"((a)[1]), "r"((a)[2]), "r"((a)[3]),        \
                   "r"(b0), "r"(b1))

// ---------------- kernel 1: scatter + fp16 convert --------------------------
// Thread ranges: [0,n) scatter; [n, n+n8i) inp convert; then weight convert.
// g_cnt is zeroed by a cudaMemsetAsync node before this kernel.
__global__ void k_prep(const float* __restrict__ inp,
                       const float* __restrict__ w,
                       const int* __restrict__ gate,
                       int n, int n8i, int n8w)
{
    int i = blockIdx.x * blockDim.x + threadIdx.x;

    if (i < n) {                                   // token -> expert slab
        int e = gate[i];
        int p = atomicAdd(&g_cnt[e], 1);
        g_idx[e * N_TOK_MAX + p] = i;
        return;
    }
    int j = i - n;
    const float* src;
    uint4* dst;
    if (j < n8i) { src = inp; dst = g_inp_h; }
    else {
        j -= n8i;
        if (j >= n8w) return;
        src = w; dst = g_w_h;
    }
    const float4* s = reinterpret_cast<const float4*>(src) + (size_t)j * 2;
    float4 a = s[0], b = s[1];
    float f[8] = {a.x, a.y, a.z, a.w, b.x, b.y, b.z, b.w};
    uint32_t hb[8];
#pragma unroll
    for (int k = 0; k < 8; k++)
        hb[k] = (uint32_t)__half_as_ushort(__float2half_rn(f[k]));
    uint4 H;
    H.x = hb[0] | (hb[1] << 16); H.y = hb[2] | (hb[3] << 16);
    H.z = hb[4] | (hb[5] << 16); H.w = hb[6] | (hb[7] << 16);
    dst[j] = H;
}

// ---------------- kernel 2: mma.sync grouped GEMM ---------------------------
// SMEM: 3 stages x 32KB (97KB/CTA -> 2 CTAs/SM); each stage: A / B tiles,
// 128 rows x 128B, chunk-XOR swizzle (c ^= row&7), conflict-free ldmatrix.
// Ring invariant: chunk kb -> stage kb % STAGES.
#define STAGES      3
#define STAGE_BYTES 32768
#define OFF_A       0
#define OFF_B       16384
#define SMEM_TOTAL  (1024 + STAGES * STAGE_BYTES)

__global__ __launch_bounds__(256, 2)
void k_gemm_mma(float* __restrict__ out)
{
    const int e   = blockIdx.z;
    const int cnt = g_cnt[e];
    const int m0  = blockIdx.y * BM;
    if (m0 >= cnt) return;
    const int n0   = blockIdx.x * BN;
    const int base = e * N_TOK_MAX;

    extern __shared__ char smem[];
    const uint32_t sbase = smem_u32(smem);
    const uint32_t tb0   = (sbase + 1023u) & ~1023u;

    const int tid    = threadIdx.x;
    const int lane   = tid & 31;
    const int wid    = tid >> 5;
    const int warp_m = wid & 3;        // 4 warps over M (32 rows each)
    const int warp_n = wid >> 2;       // 2 warps over N (64 cols each)

    // ---- cp.async loader: row = tid>>1, 4 x 16B units per row half ---------
    const int row = tid >> 1;
    const int ub  = (tid & 1) * 4;
    const int gm  = m0 + row;
    const int atok = (gm < cnt) ? g_idx[base + gm] : g_idx[base];

    const uint4* pA = g_inp_h + (size_t)atok * ROW_U4 + ub;
    const uint4* pB = g_w_h + ((size_t)e * OUT_FEAT + (n0 + row)) * ROW_U4 + ub;

    uint32_t dsw[4];
#pragma unroll
    for (int u = 0; u < 4; u++)
        dsw[u] = row * 128 + (((ub + u) ^ (row & 7)) << 4);

    // ---- ldmatrix lane addressing (non-trans) ------------------------------
    const int a_r  = warp_m * 32 + (lane & 15);
    const int a_cb = lane >> 4;
    const int b_r  = warp_n * 64 + (lane & 7) + ((lane >> 4) << 3);
    const int b_cb = (lane >> 3) & 1;

    float acc[2][8][4];
#pragma unroll
    for (int mf = 0; mf < 2; mf++)
#pragma unroll
        for (int nf = 0; nf < 8; nf++)
#pragma unroll
            for (int q = 0; q < 4; q++) acc[mf][nf][q] = 0.0f;

#define LOAD_STAGE(kb, st) do {                                               \
        const uint32_t tbs = tb0 + (st) * STAGE_BYTES;                        \
        const int kof = (kb) * 8;                                             \
        _Pragma("unroll")                                                     \
        for (int u = 0; u < 4; u++) {                                         \
            cp16(tbs + OFF_A + dsw[u], pA + kof + u);                         \
            cp16(tbs + OFF_B + dsw[u], pB + kof + u);                         \
        }                                                                     \
        CP_COMMIT();                                                          \
    } while (0)

    // 3-stage ring, chunk kb lives in stage kb%3.
    LOAD_STAGE(0, 0);
    LOAD_STAGE(1, 1);

    for (int kb = 0; kb < NCHUNK; kb++) {
        const int st = kb % STAGES;
        if (kb == NCHUNK - 1) CP_WAIT(0); else CP_WAIT(1);
        __syncthreads();
        const uint32_t tbs = tb0 + st * STAGE_BYTES;

#pragma unroll
        for (int ks = 0; ks < 4; ks++) {
            uint32_t af[2][4];
#pragma unroll
            for (int mf = 0; mf < 2; mf++) {
                const int r = a_r + mf * 16;
                const int c = ks * 2 + a_cb;
                const uint32_t off = r * 128 + ((c ^ (r & 7)) << 4);
                LDSM_X4(af[mf], tbs + OFF_A + off);
            }
            uint32_t bf[4][4];
#pragma unroll
            for (int g4 = 0; g4 < 4; g4++) {
                const int r = b_r + g4 * 16;
                const int c = ks * 2 + b_cb;
                const uint32_t off = r * 128 + ((c ^ (r & 7)) << 4);
                LDSM_X4(bf[g4], tbs + OFF_B + off);
            }
#pragma unroll
            for (int mf = 0; mf < 2; mf++)
#pragma unroll
                for (int nf = 0; nf < 8; nf++) {
                    const int g4 = nf >> 1, pp = (nf & 1) * 2;
                    MMA_F16(acc[mf][nf], af[mf], bf[g4][pp], bf[g4][pp + 1]);
                }
        }

        // prefetch chunk kb+2 into stage (kb+2)%3 = (kb-1)%3: consumed at
        // kb-1, and every warp passed this iteration's barrier after it.
        if (kb + 2 < NCHUNK) LOAD_STAGE(kb + 2, (kb + 2) % STAGES);
    }

    // ---- epilogue: scatter C rows back to token order ----------------------
    const int g = lane >> 2;
    const int t = lane & 3;
#pragma unroll
    for (int mf = 0; mf < 2; mf++) {
#pragma unroll
        for (int hh = 0; hh < 2; hh++) {
            const int m = m0 + warp_m * 32 + mf * 16 + g + hh * 8;
            if (m < cnt) {
                const int tok = g_idx[base + m];
                float* orow = out + (size_t)tok * OUT_FEAT + n0 + warp_n * 64 + t * 2;
#pragma unroll
                for (int nf = 0; nf < 8; nf++) {
                    float2 v = make_float2(acc[mf][nf][hh * 2],
                                           acc[mf][nf][hh * 2 + 1]);
                    *reinterpret_cast<float2*>(orow + nf * 8) = v;
                }
            }
        }
    }
}

// ---------------- launch -----------------------------------------------------
extern "C" void kernel_launch(void* const* d_in, const int* in_sizes, int n_in,
                              void* d_out, int out_size)
{
    const float* inp  = (const float*)d_in[0];
    const int*   gate = (const int*)d_in[1];
    const float* w    = (const float*)d_in[2];
    float*       out  = (float*)d_out;

    const int n = in_sizes[1];                       // token count

    cudaFuncSetAttribute(k_gemm_mma,
                         cudaFuncAttributeMaxDynamicSharedMemorySize, SMEM_TOTAL);

    // zero per-expert counters via a memset node (graph-capturable)
    void* cnt_ptr = nullptr;
    cudaGetSymbolAddress(&cnt_ptr, g_cnt);
    cudaMemsetAsync(cnt_ptr, 0, N_EXP * sizeof(int));

    const int n8i = n * IN_FEAT / 8;
    const int n8w = N_EXP * OUT_FEAT * IN_FEAT / 8;
    const int total = n + n8i + n8w;

    k_prep<<<(total + 255) / 256, 256>>>(inp, w, gate, n, n8i, n8w);

    dim3 grid(OUT_FEAT / BN, N_TOK_MAX / BM, N_EXP);
    k_gemm_mma<<<grid, 256, SMEM_TOTAL>>>(out);
}